// round 13
// baseline (speedup 1.0000x reference)
#include <cuda_runtime.h>
#include <cuda_bf16.h>
#include <cstdint>

// YOLO loss: warp-autonomous cp.async tiles (no block-level load barrier),
// 2 threads/cell role split, hierarchical reduction.
// pred/target: (16384, 7, 7, 30) fp32. Output: scalar fp32.

#define S 7
#define CH 30
#define TOTAL_CELLS (16384 * S * S)          // 802816
#define STEP (1.0f / 7.0f)
#define LAMBDA_COORD 5.0f
#define LAMBDA_NOOBJ 0.5f
#define EPS 1e-10f
#define INV_N (1.0f / 16384.0f)

#define TPB 256
#define WARPS (TPB / 32)                      // 8
#define CELLS_PER_WARP 16
#define CELLS_PER_BLOCK (WARPS * CELLS_PER_WARP)   // 128
#define NBLOCKS (TOTAL_CELLS / CELLS_PER_BLOCK)    // 6272

#define WARP_FLOATS (CELLS_PER_WARP * CH)     // 480 floats per array
#define WARP_VEC4 (WARP_FLOATS / 4)           // 120 float4 per array
#define WARP_SMEM_FLOATS (2 * WARP_FLOATS)    // 960 (pred | target)
#define WARP_SMEM_BYTES (WARP_SMEM_FLOATS * 4) // 3840 B

__device__ __forceinline__ uint32_t smem_u32(const void* p) {
    uint32_t a;
    asm("{ .reg .u64 t; cvta.to.shared.u64 t, %1; cvt.u32.u64 %0, t; }" : "=r"(a) : "l"(p));
    return a;
}
__device__ __forceinline__ void cp16(uint32_t dst, const void* src) {
    asm volatile("cp.async.cg.shared.global [%0], [%1], 16;" :: "r"(dst), "l"(src));
}
__device__ __forceinline__ void cp_commit() {
    asm volatile("cp.async.commit_group;" ::: "memory");
}
__device__ __forceinline__ void cp_wait0() {
    asm volatile("cp.async.wait_group 0;" ::: "memory");
}

__device__ __forceinline__ float warp_reduce(float v) {
#pragma unroll
    for (int off = 16; off > 0; off >>= 1)
        v += __shfl_xor_sync(0xFFFFFFFFu, v, off);
    return v;
}

__global__ __launch_bounds__(TPB, 6)
void yolo_loss_kernel(const float* __restrict__ pred,
                      const float* __restrict__ target,
                      float* __restrict__ out) {
    __shared__ float sm[WARPS * WARP_SMEM_FLOATS];  // 7680 floats = 30720 B
    const int tid = threadIdx.x;
    const int lane = tid & 31;
    const int w = tid >> 5;

    // ---- warp-private cp.async staging (no cross-warp coupling) ----
    const int gw = blockIdx.x * WARPS + w;           // global warp tile id
    {
        const float4* pg = reinterpret_cast<const float4*>(pred) + (size_t)gw * WARP_VEC4;
        const float4* tg = reinterpret_cast<const float4*>(target) + (size_t)gw * WARP_VEC4;
        const uint32_t pdst = smem_u32(sm) + w * WARP_SMEM_BYTES;
        const uint32_t tdst = pdst + WARP_FLOATS * 4;
        // 120 float4 per array: 3 full rounds + 24-lane tail
#pragma unroll
        for (int r = 0; r < 3; r++) {
            cp16(pdst + (lane + 32 * r) * 16, pg + lane + 32 * r);
            cp16(tdst + (lane + 32 * r) * 16, tg + lane + 32 * r);
        }
        if (lane < (WARP_VEC4 - 96)) {  // 24-lane tail
            cp16(pdst + (lane + 96) * 16, pg + lane + 96);
            cp16(tdst + (lane + 96) * 16, tg + lane + 96);
        }
        cp_commit();
    }
    cp_wait0();
    __syncwarp();

    // ---- compute: lanes 0-15 role A on cells 0-15, lanes 16-31 role B ----
    const float* wsp = sm + w * WARP_SMEM_FLOATS;          // warp's pred floats
    const float* wst = wsp + WARP_FLOATS;                  // warp's target floats
    const int c = lane & 15;                               // local cell in warp tile
    float loss = 0.0f;

    if (lane < 16) {
        // role A: channels 0..13 (boxes, IoU, conf, coord, noobj, class 10-13)
        float pv[14], tv[14];
        {
            const float2* sp2 = reinterpret_cast<const float2*>(wsp) + c * 15;
            const float2* st2 = reinterpret_cast<const float2*>(wst) + c * 15;
#pragma unroll
            for (int i = 0; i < 7; i++) {
                float2 a = sp2[i];
                pv[2 * i] = a.x; pv[2 * i + 1] = a.y;
            }
#pragma unroll
            for (int i = 0; i < 7; i++) {
                float2 a = st2[i];
                tv[2 * i] = a.x; tv[2 * i + 1] = a.y;
            }
        }

        const int cell = gw * CELLS_PER_WARP + c;
        const int rem = cell % (S * S);
        const float gy = (float)(rem / S);   // axis 1
        const float gx = (float)(rem % S);   // axis 2

        const float cell_mask = (tv[9] > 0.0f) ? 1.0f : 0.0f;

        float iou[2];
#pragma unroll
        for (int b = 0; b < 2; b++) {
            const int o = 5 * b;
            float pw = fmaxf(pv[o + 2], 0.0f);
            float ph = fmaxf(pv[o + 3], 0.0f);
            float px = fmaxf((pv[o + 0] + gx) * STEP - pv[o + 2] * 0.5f, 0.0f);
            float py = fmaxf((pv[o + 1] + gy) * STEP - pv[o + 3] * 0.5f, 0.0f);
            float tw = fmaxf(tv[o + 2], 0.0f);
            float th = fmaxf(tv[o + 3], 0.0f);
            float tx = fmaxf((tv[o + 0] + gx) * STEP - tv[o + 2] * 0.5f, 0.0f);
            float ty = fmaxf((tv[o + 1] + gy) * STEP - tv[o + 3] * 0.5f, 0.0f);

            float inter_w = fmaxf(pw + tw - (fmaxf(px + pw, tx + tw) - fminf(px, tx)), 0.0f);
            float inter_h = fmaxf(ph + th - (fmaxf(py + ph, ty + th) - fminf(py, ty)), 0.0f);
            float inter = inter_w * inter_h;
            float uni = pw * ph + tw * th - inter;
            iou[b] = inter / (uni + EPS);
        }

        const int resp = (iou[1] > iou[0]) ? 1 : 0;  // ties -> box 0

#pragma unroll
        for (int b = 0; b < 2; b++) {
            const int o = 5 * b;
            const float ob = (b == resp) ? cell_mask : 0.0f;
            float cc = 0.0f;
#pragma unroll
            for (int q = 0; q < 4; q++) {
                float d = pv[o + q] - tv[o + q];
                cc += d * d;
            }
            loss += LAMBDA_COORD * ob * cc;
            float dc = pv[o + 4] - iou[b];
            loss += ob * dc * dc;
            loss += LAMBDA_NOOBJ * (1.0f - ob) * pv[o + 4] * pv[o + 4];
        }

        float cl = 0.0f;
#pragma unroll
        for (int q = 10; q < 14; q++) {
            float d = pv[q] - tv[q];
            cl += d * d;
        }
        loss += cell_mask * cl;
    } else {
        // role B: class channels 14..29
        const float mt = wst[c * CH + 9];
        const float cell_mask = (mt > 0.0f) ? 1.0f : 0.0f;

        const float2* sp2 = reinterpret_cast<const float2*>(wsp) + c * 15 + 7;
        const float2* st2 = reinterpret_cast<const float2*>(wst) + c * 15 + 7;
        float cl = 0.0f;
#pragma unroll
        for (int i = 0; i < 8; i++) {
            float2 a = sp2[i];
            float2 b = st2[i];
            float d0 = a.x - b.x;
            float d1 = a.y - b.y;
            cl += d0 * d0 + d1 * d1;
        }
        loss = cell_mask * cl;
    }

    // ---- reduction: warp -> block -> single atomic ----
    __shared__ float warp_sums[WARPS];
    loss = warp_reduce(loss);
    if (lane == 0) warp_sums[w] = loss;
    __syncthreads();
    if (w == 0) {
        float v = (lane < WARPS) ? warp_sums[lane] : 0.0f;
        v = warp_reduce(v);
        if (lane == 0) atomicAdd(out, v * INV_N);
    }
}

extern "C" void kernel_launch(void* const* d_in, const int* in_sizes, int n_in,
                              void* d_out, int out_size) {
    const float* pred = (const float*)d_in[0];
    const float* target = (const float*)d_in[1];
    float* out = (float*)d_out;

    static bool attr_set = false;
    if (!attr_set) {
        cudaFuncSetAttribute(yolo_loss_kernel,
                             cudaFuncAttributePreferredSharedMemoryCarveout, 100);
        attr_set = true;
    }

    cudaMemsetAsync(out, 0, (size_t)out_size * sizeof(float));
    yolo_loss_kernel<<<NBLOCKS, TPB>>>(pred, target, out);
}